// round 1
// baseline (speedup 1.0000x reference)
#include <cuda_runtime.h>
#include <math.h>

#define BB 2
#define SS 2048
#define EE 2048
#define HH 16
#define DD 128
#define N3 6144            // 3*EE
#define MM (BB*SS)         // 4096
#define KK EE              // 2048

// Scratch (static device globals — allowed; no runtime allocation)
__device__ float g_qkv[(size_t)MM * N3];          // raw qkv, [b*S+s][3*E]
__device__ float g_qT[(size_t)BB * HH * DD * SS]; // Q roped+scaled, [b][h][d][s]
__device__ float g_kT[(size_t)BB * HH * DD * SS]; // K roped,        [b][h][d][s]

// ---------------------------------------------------------------------------
// Kernel 1: QKV GEMM  (M=4096, N=6144, K=2048) fp32, 128x128x16 tiles,
// 256 threads, 8x8 per-thread register tile.
// ---------------------------------------------------------------------------
__global__ __launch_bounds__(256) void qkv_gemm(const float* __restrict__ X,
                                                const float* __restrict__ W,
                                                const float* __restrict__ bias) {
    __shared__ float As[16][132];   // As[k][m], padded vs store conflicts
    __shared__ float Bs[16][128];   // Bs[k][n]

    const int tid = threadIdx.x;
    const int tx = tid & 15;
    const int ty = tid >> 4;
    const int m0 = blockIdx.y * 128;
    const int n0 = blockIdx.x * 128;

    const int arow = tid >> 2;          // 0..63
    const int acol = (tid & 3) << 2;    // 0,4,8,12
    const int brow = tid >> 5;          // 0..7
    const int bcol = (tid & 31) << 2;   // 0..124

    float acc[8][8];
    #pragma unroll
    for (int i = 0; i < 8; i++)
        #pragma unroll
        for (int j = 0; j < 8; j++) acc[i][j] = 0.0f;

    const float* Aptr = X + (size_t)m0 * KK;
    const float* Bptr = W + n0;

    for (int kt = 0; kt < KK; kt += 16) {
        #pragma unroll
        for (int r = 0; r < 2; r++) {
            float4 a = *(const float4*)(Aptr + (size_t)(arow + 64 * r) * KK + kt + acol);
            As[acol + 0][arow + 64 * r] = a.x;
            As[acol + 1][arow + 64 * r] = a.y;
            As[acol + 2][arow + 64 * r] = a.z;
            As[acol + 3][arow + 64 * r] = a.w;
        }
        #pragma unroll
        for (int r = 0; r < 2; r++) {
            float4 bv = *(const float4*)(Bptr + (size_t)(kt + brow + 8 * r) * N3 + bcol);
            *(float4*)(&Bs[brow + 8 * r][bcol]) = bv;
        }
        __syncthreads();

        #pragma unroll
        for (int k = 0; k < 16; k++) {
            float4 a0 = *(const float4*)(&As[k][ty * 8]);
            float4 a1 = *(const float4*)(&As[k][ty * 8 + 4]);
            float4 b0 = *(const float4*)(&Bs[k][tx * 8]);
            float4 b1 = *(const float4*)(&Bs[k][tx * 8 + 4]);
            float av[8] = {a0.x, a0.y, a0.z, a0.w, a1.x, a1.y, a1.z, a1.w};
            float bv[8] = {b0.x, b0.y, b0.z, b0.w, b1.x, b1.y, b1.z, b1.w};
            #pragma unroll
            for (int i = 0; i < 8; i++)
                #pragma unroll
                for (int j = 0; j < 8; j++)
                    acc[i][j] += av[i] * bv[j];
        }
        __syncthreads();
    }

    // epilogue: add bias, write g_qkv
    #pragma unroll
    for (int i = 0; i < 8; i++) {
        const int row = m0 + ty * 8 + i;
        float* outp = g_qkv + (size_t)row * N3 + n0 + tx * 8;
        float4 o0, o1;
        o0.x = acc[i][0] + bias[n0 + tx * 8 + 0];
        o0.y = acc[i][1] + bias[n0 + tx * 8 + 1];
        o0.z = acc[i][2] + bias[n0 + tx * 8 + 2];
        o0.w = acc[i][3] + bias[n0 + tx * 8 + 3];
        o1.x = acc[i][4] + bias[n0 + tx * 8 + 4];
        o1.y = acc[i][5] + bias[n0 + tx * 8 + 5];
        o1.z = acc[i][6] + bias[n0 + tx * 8 + 6];
        o1.w = acc[i][7] + bias[n0 + tx * 8 + 7];
        *(float4*)(outp) = o0;
        *(float4*)(outp + 4) = o1;
    }
}

// ---------------------------------------------------------------------------
// Kernel 2: RoPE + transpose.  Reads g_qkv, writes g_qT / g_kT in [b][h][d][s].
// Q additionally scaled by 1/sqrt(D).
// Tile: 32 s x 128 d through padded smem (coalesced both directions).
// ---------------------------------------------------------------------------
__global__ __launch_bounds__(256) void rope_transpose() {
    __shared__ float tile[32][129];
    const int s0 = blockIdx.x * 32;
    const int h = blockIdx.y;
    const int zz = blockIdx.z;      // b*2 + which (0=q, 1=k)
    const int b = zz >> 1;
    const int which = zz & 1;

    const float* src = g_qkv + ((size_t)(b * SS + s0)) * N3 + which * EE + h * DD;
    for (int idx = threadIdx.x; idx < 32 * 128; idx += 256) {
        int sl = idx >> 7, d = idx & 127;
        tile[sl][d] = src[(size_t)sl * N3 + d];
    }
    __syncthreads();

    float* dst = (which == 0 ? g_qT : g_kT) + ((size_t)(b * HH + h) * DD) * SS + s0;
    const float scale = (which == 0) ? 0.08838834764831845f : 1.0f;  // 1/sqrt(128)
    for (int idx = threadIdx.x; idx < 32 * 128; idx += 256) {
        int d = idx >> 5, sl = idx & 31;
        float u = tile[sl][d];
        float w = tile[sl][d ^ 64];
        float rh = (d < 64) ? -w : w;
        float t = (float)((s0 + sl) * 128 + d);
        float sv, cv;
        sincosf(t, &sv, &cv);
        dst[(size_t)d * SS + sl] = (u * cv + rh * sv) * scale;
    }
}

// ---------------------------------------------------------------------------
// Kernel 3: flash attention, fp32 SIMT.
// Block: 256 threads, BM=128 queries, BN=128 keys/iter, D=128.
// smem: Qt[128d][128m] + Kt[64d][128n] (2 chunks) + Vs[128n][128d] + Ps[128][128]
//     = 224 KB dynamic.
// ---------------------------------------------------------------------------
__global__ __launch_bounds__(256, 1) void attn_kernel(float* __restrict__ out) {
    extern __shared__ float sm[];
    float* Qt = sm;                    // 16384 floats
    float* Kt = Qt + 128 * 128;        //  8192 floats
    float* Vs = Kt + 64 * 128;         // 16384 floats
    float* Ps = Vs + 128 * 128;        // 16384 floats

    const int tid = threadIdx.x;
    const int tx = tid & 15;
    const int ty = tid >> 4;
    const int s0 = blockIdx.x * 128;
    const int h = blockIdx.y;
    const int b = blockIdx.z;

    const float* qbase = g_qT + (size_t)(b * HH + h) * DD * SS;
    const float* kbase = g_kT + (size_t)(b * HH + h) * DD * SS;
    const float* vbase = g_qkv + (size_t)b * SS * N3 + 2 * EE + h * DD;

    // Load Q tile (transposed layout already): Qt[d][m]
    #pragma unroll
    for (int i = 0; i < 16; i++) {
        int lin = tid + i * 256;          // f4 index, 4096 total
        int d = lin >> 5;
        int m = (lin & 31) << 2;
        float4 v = *(const float4*)(qbase + (size_t)d * SS + s0 + m);
        *(float4*)(&Qt[d * 128 + m]) = v;
    }

    float O[8][8];
    #pragma unroll
    for (int i = 0; i < 8; i++)
        #pragma unroll
        for (int j = 0; j < 8; j++) O[i][j] = 0.0f;
    float mrow[8], lrow[8];
    #pragma unroll
    for (int i = 0; i < 8; i++) { mrow[i] = -1e30f; lrow[i] = 0.0f; }

    for (int kt = 0; kt < SS / 128; kt++) {
        const int n0 = kt * 128;
        __syncthreads();   // protect Vs/Kt/Ps from previous iteration's readers

        // Load V tile: Vs[n][dv]
        #pragma unroll
        for (int i = 0; i < 16; i++) {
            int lin = tid + i * 256;
            int n = lin >> 5;
            int dv = (lin & 31) << 2;
            float4 v = *(const float4*)(vbase + (size_t)(n0 + n) * N3 + dv);
            *(float4*)(&Vs[n * 128 + dv]) = v;
        }
        // Load K chunk 0 (d = 0..63): Kt[d][n]
        #pragma unroll
        for (int i = 0; i < 8; i++) {
            int lin = tid + i * 256;
            int d = lin >> 5;
            int m = (lin & 31) << 2;
            float4 v = *(const float4*)(kbase + (size_t)d * SS + n0 + m);
            *(float4*)(&Kt[d * 128 + m]) = v;
        }
        __syncthreads();

        float sacc[8][8];
        #pragma unroll
        for (int i = 0; i < 8; i++)
            #pragma unroll
            for (int j = 0; j < 8; j++) sacc[i][j] = 0.0f;

        // QK^T chunk 0
        #pragma unroll 4
        for (int d = 0; d < 64; d++) {
            float4 a0 = *(const float4*)(&Qt[d * 128 + ty * 8]);
            float4 a1 = *(const float4*)(&Qt[d * 128 + ty * 8 + 4]);
            float4 b0 = *(const float4*)(&Kt[d * 128 + tx * 8]);
            float4 b1 = *(const float4*)(&Kt[d * 128 + tx * 8 + 4]);
            float av[8] = {a0.x, a0.y, a0.z, a0.w, a1.x, a1.y, a1.z, a1.w};
            float bv[8] = {b0.x, b0.y, b0.z, b0.w, b1.x, b1.y, b1.z, b1.w};
            #pragma unroll
            for (int i = 0; i < 8; i++)
                #pragma unroll
                for (int j = 0; j < 8; j++) sacc[i][j] += av[i] * bv[j];
        }
        __syncthreads();
        // Load K chunk 1 (d = 64..127)
        #pragma unroll
        for (int i = 0; i < 8; i++) {
            int lin = tid + i * 256;
            int d = lin >> 5;
            int m = (lin & 31) << 2;
            float4 v = *(const float4*)(kbase + (size_t)(64 + d) * SS + n0 + m);
            *(float4*)(&Kt[d * 128 + m]) = v;
        }
        __syncthreads();
        // QK^T chunk 1
        #pragma unroll 4
        for (int d = 0; d < 64; d++) {
            float4 a0 = *(const float4*)(&Qt[(64 + d) * 128 + ty * 8]);
            float4 a1 = *(const float4*)(&Qt[(64 + d) * 128 + ty * 8 + 4]);
            float4 b0 = *(const float4*)(&Kt[d * 128 + tx * 8]);
            float4 b1 = *(const float4*)(&Kt[d * 128 + tx * 8 + 4]);
            float av[8] = {a0.x, a0.y, a0.z, a0.w, a1.x, a1.y, a1.z, a1.w};
            float bv[8] = {b0.x, b0.y, b0.z, b0.w, b1.x, b1.y, b1.z, b1.w};
            #pragma unroll
            for (int i = 0; i < 8; i++)
                #pragma unroll
                for (int j = 0; j < 8; j++) sacc[i][j] += av[i] * bv[j];
        }

        // Online softmax update (scale already folded into Q)
        #pragma unroll
        for (int i = 0; i < 8; i++) {
            float mx = sacc[i][0];
            #pragma unroll
            for (int j = 1; j < 8; j++) mx = fmaxf(mx, sacc[i][j]);
            #pragma unroll
            for (int off = 8; off > 0; off >>= 1)
                mx = fmaxf(mx, __shfl_xor_sync(0xffffffffu, mx, off));
            float mnew = fmaxf(mrow[i], mx);
            float alpha = __expf(mrow[i] - mnew);
            float p[8];
            float ps = 0.0f;
            #pragma unroll
            for (int j = 0; j < 8; j++) {
                p[j] = __expf(sacc[i][j] - mnew);
                ps += p[j];
            }
            float4 p0 = {p[0], p[1], p[2], p[3]};
            float4 p1 = {p[4], p[5], p[6], p[7]};
            *(float4*)(&Ps[(ty * 8 + i) * 128 + tx * 8]) = p0;
            *(float4*)(&Ps[(ty * 8 + i) * 128 + tx * 8 + 4]) = p1;
            #pragma unroll
            for (int off = 8; off > 0; off >>= 1)
                ps += __shfl_xor_sync(0xffffffffu, ps, off);
            lrow[i] = lrow[i] * alpha + ps;
            mrow[i] = mnew;
            #pragma unroll
            for (int j = 0; j < 8; j++) O[i][j] *= alpha;
        }
        __syncthreads();

        // O += P @ V
        #pragma unroll 2
        for (int k = 0; k < 128; k++) {
            float4 v0 = *(const float4*)(&Vs[k * 128 + tx * 8]);
            float4 v1 = *(const float4*)(&Vs[k * 128 + tx * 8 + 4]);
            float vv[8] = {v0.x, v0.y, v0.z, v0.w, v1.x, v1.y, v1.z, v1.w};
            #pragma unroll
            for (int i = 0; i < 8; i++) {
                float p = Ps[(ty * 8 + i) * 128 + k];
                #pragma unroll
                for (int j = 0; j < 8; j++) O[i][j] += p * vv[j];
            }
        }
    }

    // Epilogue: normalize and write out[b][s][h][d]
    #pragma unroll
    for (int i = 0; i < 8; i++) {
        float inv = 1.0f / lrow[i];
        int s = s0 + ty * 8 + i;
        float* op = out + ((size_t)(b * SS + s) * HH + h) * DD + tx * 8;
        float4 o0, o1;
        o0.x = O[i][0] * inv; o0.y = O[i][1] * inv;
        o0.z = O[i][2] * inv; o0.w = O[i][3] * inv;
        o1.x = O[i][4] * inv; o1.y = O[i][5] * inv;
        o1.z = O[i][6] * inv; o1.w = O[i][7] * inv;
        *(float4*)(op) = o0;
        *(float4*)(op + 4) = o1;
    }
}

// ---------------------------------------------------------------------------
extern "C" void kernel_launch(void* const* d_in, const int* in_sizes, int n_in,
                              void* d_out, int out_size) {
    const float* x    = (const float*)d_in[0];
    const float* W    = (const float*)d_in[1];
    const float* bias = (const float*)d_in[2];
    float* out = (float*)d_out;

    dim3 g1(N3 / 128, MM / 128);        // 48 x 32
    qkv_gemm<<<g1, 256>>>(x, W, bias);

    dim3 g2(SS / 32, HH, BB * 2);       // 64 x 16 x 4
    rope_transpose<<<g2, 256>>>();

    const int attn_smem = (128 * 128 + 64 * 128 + 128 * 128 + 128 * 128) * 4; // 229376
    cudaFuncSetAttribute(attn_kernel, cudaFuncAttributeMaxDynamicSharedMemorySize, attn_smem);
    dim3 g3(SS / 128, HH, BB);          // 16 x 16 x 2
    attn_kernel<<<g3, 256, attn_smem>>>(out);
}